// round 9
// baseline (speedup 1.0000x reference)
#include <cuda_runtime.h>
#include <cuda_bf16.h>
#include <math.h>
#include <stdint.h>

// Problem constants
#define BB 2
#define SS 2048
#define DD 1024
#define HH 16
#define DKK 64
#define MM (BB * SS)          // 4096
#define SCALE 0.125f          // 1/sqrt(64)

// Scratch (allocation-free rule: __device__ globals)
__device__ __nv_bfloat16 g_Qhi[BB * HH * SS * DKK];  // post-RoPE hi/lo
__device__ __nv_bfloat16 g_Qlo[BB * HH * SS * DKK];
__device__ __nv_bfloat16 g_Khi[BB * HH * SS * DKK];
__device__ __nv_bfloat16 g_Klo[BB * HH * SS * DKK];
__device__ __nv_bfloat16 g_Vthi[BB * HH * DKK * SS]; // V transposed [b,h,dk,s]
__device__ __nv_bfloat16 g_Vtlo[BB * HH * DKK * SS];
__device__ float g_O[BB * SS * DD];                  // attention out fp32
__device__ int8_t g_xq1[MM * DD];    // x quantized hi/lo
__device__ int8_t g_xq0[MM * DD];
__device__ float  g_sx[MM];
__device__ int8_t g_aq1[MM * DD];    // attention-out quantized
__device__ int8_t g_aq0[MM * DD];
__device__ float  g_sa[MM];
__device__ int8_t g_w1[3 * DD * DD]; // W^T quantized (QKV fused / reused for O)
__device__ int8_t g_w0[3 * DD * DD];
__device__ float  g_sw[3 * DD];

// ---------------------------------------------------------------------------
// Helpers
// ---------------------------------------------------------------------------
__device__ __forceinline__ uint32_t s2u(const void* p) {
    uint32_t a;
    asm("{ .reg .u64 t; cvta.to.shared.u64 t, %1; cvt.u32.u64 %0, t; }"
        : "=r"(a) : "l"(p));
    return a;
}
__device__ __forceinline__ void cp16(uint32_t dst, const void* src) {
    asm volatile("cp.async.cg.shared.global [%0], [%1], 16;" :: "r"(dst), "l"(src));
}
#define CP_COMMIT() asm volatile("cp.async.commit_group;" ::: "memory")
#define CP_WAIT1()  asm volatile("cp.async.wait_group 1;" ::: "memory")

__device__ __forceinline__ void mma16816(float* c, const uint32_t* a, const uint32_t* b)
{
    asm volatile(
        "mma.sync.aligned.m16n8k16.row.col.f32.bf16.bf16.f32 "
        "{%0,%1,%2,%3}, {%4,%5,%6,%7}, {%8,%9}, {%0,%1,%2,%3};"
        : "+f"(c[0]), "+f"(c[1]), "+f"(c[2]), "+f"(c[3])
        : "r"(a[0]), "r"(a[1]), "r"(a[2]), "r"(a[3]), "r"(b[0]), "r"(b[1]));
}
__device__ __forceinline__ void imma16832(int* c, const uint32_t* a, const uint32_t* b)
{
    asm volatile(
        "mma.sync.aligned.m16n8k32.row.col.s32.s8.s8.s32 "
        "{%0,%1,%2,%3}, {%4,%5,%6,%7}, {%8,%9}, {%0,%1,%2,%3};"
        : "+r"(c[0]), "+r"(c[1]), "+r"(c[2]), "+r"(c[3])
        : "r"(a[0]), "r"(a[1]), "r"(a[2]), "r"(a[3]), "r"(b[0]), "r"(b[1]));
}
__device__ __forceinline__ uint32_t pack_bf2(float a, float b) {
    __nv_bfloat162 t = __floats2bfloat162_rn(a, b);
    return *(uint32_t*)&t;
}

// ---------------------------------------------------------------------------
// Quantize rows: per-row absmax, v = s*(128*a1 + a0). 1024 cols fixed.
// ---------------------------------------------------------------------------
__global__ __launch_bounds__(256) void quant_rows(
    const float* __restrict__ src, int8_t* __restrict__ q1,
    int8_t* __restrict__ q0, float* __restrict__ sc)
{
    __shared__ float wm[8];
    __shared__ float s_sh;
    const int r = blockIdx.x;
    const int t = threadIdx.x;
    float4 v = *(const float4*)(src + (size_t)r * DD + t * 4);
    float f[4] = {v.x, v.y, v.z, v.w};
    float m = fmaxf(fmaxf(fabsf(f[0]), fabsf(f[1])), fmaxf(fabsf(f[2]), fabsf(f[3])));
#pragma unroll
    for (int off = 16; off; off >>= 1)
        m = fmaxf(m, __shfl_xor_sync(0xffffffffu, m, off));
    if ((t & 31) == 0) wm[t >> 5] = m;
    __syncthreads();
    if (t == 0) {
        float mm = wm[0];
#pragma unroll
        for (int j = 1; j < 8; ++j) mm = fmaxf(mm, wm[j]);
        float s = fmaxf(mm, 1e-30f) * (1.0f / 16256.0f);
        s_sh = s;
        sc[r] = s;
    }
    __syncthreads();
    const float is = 1.0f / s_sh;
    char c1[4], c0[4];
#pragma unroll
    for (int j = 0; j < 4; ++j) {
        float q = f[j] * is;
        float a1 = rintf(q * 0.0078125f);
        float a0 = rintf(q - 128.0f * a1);
        c1[j] = (char)(int)a1;
        c0[j] = (char)(int)a0;
    }
    *(uint32_t*)(q1 + (size_t)r * DD + t * 4) = *(uint32_t*)c1;
    *(uint32_t*)(q0 + (size_t)r * DD + t * 4) = *(uint32_t*)c0;
}

// ---------------------------------------------------------------------------
// Per-output-column absmax of W[k][n] -> scale
// ---------------------------------------------------------------------------
__global__ __launch_bounds__(256) void colmax_w(
    const float* __restrict__ W, float* __restrict__ sw)
{
    __shared__ float red[8][32];
    const int tx = threadIdx.x, ty = threadIdx.y;
    const int c = blockIdx.x * 32 + tx;
    float m = 0.f;
    for (int k = ty; k < DD; k += 8)
        m = fmaxf(m, fabsf(W[(size_t)k * DD + c]));
    red[ty][tx] = m;
    __syncthreads();
    if (ty == 0) {
#pragma unroll
        for (int j = 1; j < 8; ++j) m = fmaxf(m, red[j][tx]);
        sw[c] = fmaxf(m, 1e-30f) * (1.0f / 16256.0f);
    }
}

// ---------------------------------------------------------------------------
// W[k][n] -> Wt[n][k] int8 hi/lo (tiled transpose + quantize)
// ---------------------------------------------------------------------------
__global__ __launch_bounds__(256) void quantw_t(
    const float* __restrict__ W, const float* __restrict__ sw,
    int8_t* __restrict__ w1, int8_t* __restrict__ w0)
{
    __shared__ float t[32][33];
    const int tx = threadIdx.x, ty = threadIdx.y;
    const int kin = blockIdx.y * 32;
    const int nin = blockIdx.x * 32;
#pragma unroll
    for (int j = 0; j < 4; ++j)
        t[ty + j * 8][tx] = W[(size_t)(kin + ty + j * 8) * DD + nin + tx];
    __syncthreads();
#pragma unroll
    for (int j = 0; j < 4; ++j) {
        const int n = nin + ty + j * 8;
        float v = t[tx][ty + j * 8];
        float is = 1.0f / sw[n];
        float q = v * is;
        float a1 = rintf(q * 0.0078125f);
        float a0 = rintf(q - 128.0f * a1);
        size_t o = (size_t)n * DD + kin + tx;
        w1[o] = (char)(int)a1;
        w0[o] = (char)(int)a0;
    }
}

// ---------------------------------------------------------------------------
// int8x3 IMMA GEMM: CTA 128x128, 8 warps (2x4 -> 64x32 each), BK=64 bytes,
// cp.async double buffer, pitch 80B.
// QKV=true: fused N=3072 (Q/K/V select by n0), RoPE in epilogue, bf16 hi/lo out.
// QKV=false: fp32 out [m][n] + bias.
// ---------------------------------------------------------------------------
#define GEMM_SMEM 81920

template <bool QKV>
__global__ __launch_bounds__(256, 1) void i8_gemm(
    const int8_t* __restrict__ Aq1, const int8_t* __restrict__ Aq0,
    const float* __restrict__ sA,
    const int8_t* __restrict__ Bq1, const int8_t* __restrict__ Bq0,
    const float* __restrict__ sB,
    const float* __restrict__ bias_q, const float* __restrict__ bias_k,
    const float* __restrict__ bias_v,
    const int* __restrict__ pos, float* __restrict__ out)
{
    extern __shared__ char smem[];
    const uint32_t smem_u = s2u(smem);
    const int tid = threadIdx.x;
    const int lane = tid & 31;
    const int wid = tid >> 5;
    const int g = lane >> 2;
    const int tg = lane & 3;
    const int warp_m = wid & 1;
    const int warp_n = wid >> 1;
    const int n0 = blockIdx.x * 128;
    const int m0 = blockIdx.y * 128;

    int accH[4][4][4] = {};
    int accM[4][4][4] = {};

    const int r_ = tid >> 2, c4 = tid & 3;   // 64 rows x 4 vecs

    auto load_stage = [&](int st, int kc) {
        const int k0 = kc * 64;
        const uint32_t sb = smem_u + st * 40960;
        {
            uint32_t d = sb + r_ * 80 + c4 * 16;
            size_t ga = (size_t)(m0 + r_) * DD + k0 + c4 * 16;
            cp16(d, Aq1 + ga);
            cp16(d + 10240, Aq0 + ga);
            cp16(d + 64 * 80, Aq1 + ga + (size_t)64 * DD);
            cp16(d + 64 * 80 + 10240, Aq0 + ga + (size_t)64 * DD);
        }
        {
            uint32_t d = sb + 20480 + r_ * 80 + c4 * 16;
            size_t gb = (size_t)(n0 + r_) * DD + k0 + c4 * 16;
            cp16(d, Bq1 + gb);
            cp16(d + 10240, Bq0 + gb);
            cp16(d + 64 * 80, Bq1 + gb + (size_t)64 * DD);
            cp16(d + 64 * 80 + 10240, Bq0 + gb + (size_t)64 * DD);
        }
    };

    load_stage(0, 0); CP_COMMIT();
    load_stage(1, 1); CP_COMMIT();

    for (int kc = 0; kc < 16; ++kc) {
        const int st = kc & 1;
        CP_WAIT1();
        __syncthreads();

        const char* sA_ = smem + st * 40960 + (warp_m * 64) * 80;
        const char* sB_ = smem + st * 40960 + 20480 + (warp_n * 32) * 80;

#pragma unroll
        for (int ks = 0; ks < 2; ++ks) {
            const int kb = ks * 32 + tg * 4;

            uint32_t b1[4][2], b0[4][2];
#pragma unroll
            for (int nt = 0; nt < 4; ++nt) {
                const char* p = sB_ + (nt * 8 + g) * 80 + kb;
                b1[nt][0] = *(const uint32_t*)p;
                b1[nt][1] = *(const uint32_t*)(p + 16);
                const char* p2 = p + 10240;
                b0[nt][0] = *(const uint32_t*)p2;
                b0[nt][1] = *(const uint32_t*)(p2 + 16);
            }
            uint32_t a1[4][4], a0[4][4];
#pragma unroll
            for (int mt = 0; mt < 4; ++mt) {
                const char* p = sA_ + (mt * 16 + g) * 80 + kb;
                a1[mt][0] = *(const uint32_t*)p;
                a1[mt][1] = *(const uint32_t*)(p + 640);
                a1[mt][2] = *(const uint32_t*)(p + 16);
                a1[mt][3] = *(const uint32_t*)(p + 656);
                const char* p2 = p + 10240;
                a0[mt][0] = *(const uint32_t*)p2;
                a0[mt][1] = *(const uint32_t*)(p2 + 640);
                a0[mt][2] = *(const uint32_t*)(p2 + 16);
                a0[mt][3] = *(const uint32_t*)(p2 + 656);
            }
#pragma unroll
            for (int mt = 0; mt < 4; ++mt)
#pragma unroll
                for (int nt = 0; nt < 4; ++nt) {
                    imma16832(accH[mt][nt], a1[mt], b1[nt]);
                    imma16832(accM[mt][nt], a1[mt], b0[nt]);
                    imma16832(accM[mt][nt], a0[mt], b1[nt]);
                }
        }

        __syncthreads();
        if (kc + 2 < 16) load_stage(st, kc + 2);
        CP_COMMIT();
    }

    // ---- epilogue ----
    const int sec = n0 >> 10;   // 0=Q 1=K 2=V (uniform per CTA)
    int pv[4][2];
    if (QKV && sec < 2) {
#pragma unroll
        for (int mt = 0; mt < 4; ++mt) {
            const int m = m0 + warp_m * 64 + mt * 16 + g;
            const int b_ = m >> 11, s = m & 2047;
            pv[mt][0] = pos[b_ * SS + s];
            pv[mt][1] = pos[b_ * SS + s + 8];
        }
    }

#pragma unroll
    for (int nt = 0; nt < 4; ++nt) {
        const int nc = n0 + warp_n * 32 + nt * 8 + tg * 2;
        const float sb0 = sB[nc], sb1 = sB[nc + 1];
        const int nl = nc & 1023;
        const int hh = nl >> 6, dk = nl & 63;

        float invf = 0.f, bv0 = 0.f, bv1 = 0.f;
        if (QKV) {
            const float* bp = (sec == 0) ? bias_q : (sec == 1) ? bias_k : bias_v;
            bv0 = __ldg(bp + nl);
            bv1 = __ldg(bp + nl + 1);
            if (sec < 2)
                invf = (float)exp(-(double)(dk >> 1) * 0.28782313662425575);
        } else {
            bv0 = __ldg(bias_q + nc);
            bv1 = __ldg(bias_q + nc + 1);
        }

#pragma unroll
        for (int mt = 0; mt < 4; ++mt) {
            const int m = m0 + warp_m * 64 + mt * 16 + g;
            const float sa0 = sA[m], sa8 = sA[m + 8];
            const int* aH = accH[mt][nt];
            const int* aM = accM[mt][nt];
            float c00 = sa0 * sb0 * ((float)aH[0] * 16384.f + (float)aM[0] * 128.f) + bv0;
            float c01 = sa0 * sb1 * ((float)aH[1] * 16384.f + (float)aM[1] * 128.f) + bv1;
            float c10 = sa8 * sb0 * ((float)aH[2] * 16384.f + (float)aM[2] * 128.f) + bv0;
            float c11 = sa8 * sb1 * ((float)aH[3] * 16384.f + (float)aM[3] * 128.f) + bv1;

            if (!QKV) {
                *(float2*)(out + (size_t)m * DD + nc) = make_float2(c00, c01);
                *(float2*)(out + (size_t)(m + 8) * DD + nc) = make_float2(c10, c11);
                continue;
            }

            const int b_ = m >> 11, s = m & 2047;
            if (sec < 2) {
                // RoPE rotate pairs, write bf16 hi/lo [b,h,s,dk]
                float cs, sn;
                sincosf((float)pv[mt][0] * invf, &sn, &cs);
                float r00 = c00 * cs - c01 * sn;
                float r01 = c00 * sn + c01 * cs;
                sincosf((float)pv[mt][1] * invf, &sn, &cs);
                float r10 = c10 * cs - c11 * sn;
                float r11 = c10 * sn + c11 * cs;

                __nv_bfloat16* Hi = (sec == 0) ? g_Qhi : g_Khi;
                __nv_bfloat16* Lo = (sec == 0) ? g_Qlo : g_Klo;
                size_t base = (((size_t)(b_ * HH + hh) * SS) + s) * DKK + dk;
                uint32_t h2 = pack_bf2(r00, r01);
                *(uint32_t*)(Hi + base) = h2;
                __nv_bfloat162 hv = *(__nv_bfloat162*)&h2;
                *(uint32_t*)(Lo + base) =
                    pack_bf2(r00 - __bfloat162float(hv.x), r01 - __bfloat162float(hv.y));
                h2 = pack_bf2(r10, r11);
                *(uint32_t*)(Hi + base + 8 * DKK) = h2;
                hv = *(__nv_bfloat162*)&h2;
                *(uint32_t*)(Lo + base + 8 * DKK) =
                    pack_bf2(r10 - __bfloat162float(hv.x), r11 - __bfloat162float(hv.y));
            } else {
                // V: bf16 hi/lo transposed [b,h,dk,s]
                size_t base = (((size_t)(b_ * HH + hh) * DKK) + dk) * SS + s;
                float vv[4] = {c00, c01, c10, c11};
                size_t off[4] = {base, base + SS, base + 8, base + SS + 8};
#pragma unroll
                for (int e = 0; e < 4; ++e) {
                    __nv_bfloat16 hb = __float2bfloat16(vv[e]);
                    g_Vthi[off[e]] = hb;
                    g_Vtlo[off[e]] = __float2bfloat16(vv[e] - __bfloat162float(hb));
                }
            }
        }
    }
}

// ---------------------------------------------------------------------------
// Flash attention with HMMA (bf16x3). CTA = 64 q-rows of one (b,h);
// 128 threads, 4 warps. Output fp32 to g_O.
// ---------------------------------------------------------------------------
#define FL_PITCH 144
#define FL_TILE (64 * FL_PITCH)
#define FL_STAGE (4 * FL_TILE)
#define FL_SMEM (2 * FL_STAGE)

__global__ __launch_bounds__(128) void flash_mma()
{
    extern __shared__ char smem[];
    const int qt = (int)gridDim.x - 1 - (int)blockIdx.x;
    const int h = blockIdx.y;
    const int b = blockIdx.z;
    const int q0 = qt * 64;
    const int tid = threadIdx.x;
    const int lane = tid & 31;
    const int w = tid >> 5;
    const int g = lane >> 2;
    const int tg = lane & 3;

    const size_t bh = (size_t)(b * HH + h);
    const __nv_bfloat16* Qhi = g_Qhi + bh * SS * DKK;
    const __nv_bfloat16* Qlo = g_Qlo + bh * SS * DKK;
    const __nv_bfloat16* Khi = g_Khi + bh * SS * DKK;
    const __nv_bfloat16* Klo = g_Klo + bh * SS * DKK;
    const __nv_bfloat16* Vthi = g_Vthi + bh * DKK * SS;
    const __nv_bfloat16* Vtlo = g_Vtlo + bh * DKK * SS;

    const int qrow = q0 + w * 16 + g;
    uint32_t qh[4][4], ql[4][4];
#pragma unroll
    for (int kc = 0; kc < 4; ++kc) {
        size_t p0 = (size_t)qrow * DKK + kc * 16 + tg * 2;
        qh[kc][0] = *(const uint32_t*)(Qhi + p0);
        qh[kc][1] = *(const uint32_t*)(Qhi + p0 + 8 * DKK);
        qh[kc][2] = *(const uint32_t*)(Qhi + p0 + 8);
        qh[kc][3] = *(const uint32_t*)(Qhi + p0 + 8 * DKK + 8);
        ql[kc][0] = *(const uint32_t*)(Qlo + p0);
        ql[kc][1] = *(const uint32_t*)(Qlo + p0 + 8 * DKK);
        ql[kc][2] = *(const uint32_t*)(Qlo + p0 + 8);
        ql[kc][3] = *(const uint32_t*)(Qlo + p0 + 8 * DKK + 8);
    }

    auto load_stage = [&](int st, int t) {
        const int j0 = t * 64;
        char* sb = smem + st * FL_STAGE;
#pragma unroll
        for (int i = 0; i < 4; ++i) {
            int v = i * 128 + tid;
            int r = v >> 3, c = v & 7;
            uint32_t d = s2u(sb + r * FL_PITCH + c * 16);
            size_t ksrc = (size_t)(j0 + r) * DKK + c * 8;
            cp16(d, Khi + ksrc);
            cp16(d + FL_TILE, Klo + ksrc);
            size_t vsrc = (size_t)r * SS + j0 + c * 8;
            cp16(d + 2 * FL_TILE, Vthi + vsrc);
            cp16(d + 3 * FL_TILE, Vtlo + vsrc);
        }
    };

    float o[8][4] = {};
    float m_g = -1e30f, m_g8 = -1e30f;
    float l_g = 0.f, l_g8 = 0.f;

    const int nT = qt + 1;
    load_stage(0, 0); CP_COMMIT();
    if (nT > 1) load_stage(1, 1);
    CP_COMMIT();

    for (int t = 0; t < nT; ++t) {
        const int st = t & 1;
        CP_WAIT1();
        __syncthreads();

        const char* sK  = smem + st * FL_STAGE;
        const char* sKl = sK + FL_TILE;
        const char* sV  = sK + 2 * FL_TILE;
        const char* sVl = sK + 3 * FL_TILE;
        const int j0 = t * 64;

        float s[8][4] = {};
#pragma unroll
        for (int kc = 0; kc < 4; ++kc) {
            const int kb = kc * 32 + tg * 4;
            uint32_t kh[8][2], kl[8][2];
#pragma unroll
            for (int nf = 0; nf < 8; ++nf) {
                const char* p = sK + (nf * 8 + g) * FL_PITCH + kb;
                kh[nf][0] = *(const uint32_t*)p;
                kh[nf][1] = *(const uint32_t*)(p + 16);
                const char* p2 = sKl + (nf * 8 + g) * FL_PITCH + kb;
                kl[nf][0] = *(const uint32_t*)p2;
                kl[nf][1] = *(const uint32_t*)(p2 + 16);
            }
#pragma unroll
            for (int nf = 0; nf < 8; ++nf) {
                mma16816(s[nf], qh[kc], kh[nf]);
                mma16816(s[nf], qh[kc], kl[nf]);
                mma16816(s[nf], ql[kc], kh[nf]);
            }
        }

        const bool diag = (t == qt);
#pragma unroll
        for (int nf = 0; nf < 8; ++nf) {
#pragma unroll
            for (int e = 0; e < 4; ++e) {
                float v = s[nf][e] * SCALE;
                if (diag) {
                    int col = j0 + nf * 8 + tg * 2 + (e & 1);
                    int row = qrow + ((e >> 1) << 3);
                    if (col > row) v = -1e30f;
                }
                s[nf][e] = v;
            }
        }

        float tm_g = -1e30f, tm_g8 = -1e30f;
#pragma unroll
        for (int nf = 0; nf < 8; ++nf) {
            tm_g  = fmaxf(tm_g,  fmaxf(s[nf][0], s[nf][1]));
            tm_g8 = fmaxf(tm_g8, fmaxf(s[nf][2], s[nf][3]));
        }
        tm_g  = fmaxf(tm_g,  __shfl_xor_sync(0xffffffffu, tm_g, 1));
        tm_g  = fmaxf(tm_g,  __shfl_xor_sync(0xffffffffu, tm_g, 2));
        tm_g8 = fmaxf(tm_g8, __shfl_xor_sync(0xffffffffu, tm_g8, 1));
        tm_g8 = fmaxf(tm_g8, __shfl_xor_sync(0xffffffffu, tm_g8, 2));

        float mn_g = fmaxf(m_g, tm_g);
        float mn_g8 = fmaxf(m_g8, tm_g8);
        float alpha_g = expf(m_g - mn_g);
        float alpha_g8 = expf(m_g8 - mn_g8);
        m_g = mn_g; m_g8 = mn_g8;

        float sum_g = 0.f, sum_g8 = 0.f;
#pragma unroll
        for (int nf = 0; nf < 8; ++nf) {
            s[nf][0] = expf(s[nf][0] - mn_g);
            s[nf][1] = expf(s[nf][1] - mn_g);
            s[nf][2] = expf(s[nf][2] - mn_g8);
            s[nf][3] = expf(s[nf][3] - mn_g8);
            sum_g += s[nf][0] + s[nf][1];
            sum_g8 += s[nf][2] + s[nf][3];
        }
        sum_g  += __shfl_xor_sync(0xffffffffu, sum_g, 1);
        sum_g  += __shfl_xor_sync(0xffffffffu, sum_g, 2);
        sum_g8 += __shfl_xor_sync(0xffffffffu, sum_g8, 1);
        sum_g8 += __shfl_xor_sync(0xffffffffu, sum_g8, 2);
        l_g = l_g * alpha_g + sum_g;
        l_g8 = l_g8 * alpha_g8 + sum_g8;

#pragma unroll
        for (int nf = 0; nf < 8; ++nf) {
            o[nf][0] *= alpha_g;
            o[nf][1] *= alpha_g;
            o[nf][2] *= alpha_g8;
            o[nf][3] *= alpha_g8;
        }

#pragma unroll
        for (int kc = 0; kc < 4; ++kc) {
            uint32_t ph[4], pl[4];
            {
                const float* s0 = s[2 * kc];
                const float* s1 = s[2 * kc + 1];
                float h0 = __bfloat162float(__float2bfloat16(s0[0]));
                float h1 = __bfloat162float(__float2bfloat16(s0[1]));
                float h2 = __bfloat162float(__float2bfloat16(s0[2]));
                float h3 = __bfloat162float(__float2bfloat16(s0[3]));
                float h4 = __bfloat162float(__float2bfloat16(s1[0]));
                float h5 = __bfloat162float(__float2bfloat16(s1[1]));
                float h6 = __bfloat162float(__float2bfloat16(s1[2]));
                float h7 = __bfloat162float(__float2bfloat16(s1[3]));
                ph[0] = pack_bf2(h0, h1);
                ph[1] = pack_bf2(h2, h3);
                ph[2] = pack_bf2(h4, h5);
                ph[3] = pack_bf2(h6, h7);
                pl[0] = pack_bf2(s0[0] - h0, s0[1] - h1);
                pl[1] = pack_bf2(s0[2] - h2, s0[3] - h3);
                pl[2] = pack_bf2(s1[0] - h4, s1[1] - h5);
                pl[3] = pack_bf2(s1[2] - h6, s1[3] - h7);
            }
            const int kb = kc * 32 + tg * 4;
            uint32_t vh[8][2], vl[8][2];
#pragma unroll
            for (int nf = 0; nf < 8; ++nf) {
                const char* p = sV + (nf * 8 + g) * FL_PITCH + kb;
                vh[nf][0] = *(const uint32_t*)p;
                vh[nf][1] = *(const uint32_t*)(p + 16);
                const char* p2 = sVl + (nf * 8 + g) * FL_PITCH + kb;
                vl[nf][0] = *(const uint32_t*)p2;
                vl[nf][1] = *(const uint32_t*)(p2 + 16);
            }
#pragma unroll
            for (int nf = 0; nf < 8; ++nf) {
                mma16816(o[nf], ph, vh[nf]);
                mma16816(o[nf], ph, vl[nf]);
                mma16816(o[nf], pl, vh[nf]);
            }
        }

        __syncthreads();
        if (t + 2 < nT) load_stage(st, t + 2);
        CP_COMMIT();
    }

    const float inv_g = 1.0f / l_g;
    const float inv_g8 = 1.0f / l_g8;
#pragma unroll
    for (int nf = 0; nf < 8; ++nf) {
        const int col = h * DKK + nf * 8 + tg * 2;
        size_t a0 = ((size_t)b * SS + qrow) * DD + col;
        *(float2*)(g_O + a0) = make_float2(o[nf][0] * inv_g, o[nf][1] * inv_g);
        size_t a8 = ((size_t)b * SS + qrow + 8) * DD + col;
        *(float2*)(g_O + a8) = make_float2(o[nf][2] * inv_g8, o[nf][3] * inv_g8);
    }
}

// ---------------------------------------------------------------------------
extern "C" void kernel_launch(void* const* d_in, const int* in_sizes, int n_in,
                              void* d_out, int out_size)
{
    const float* x  = (const float*)d_in[0];
    const int*   tp = (const int*)d_in[1];
    const float* Wq = (const float*)d_in[2];
    const float* bq = (const float*)d_in[3];
    const float* Wk = (const float*)d_in[4];
    const float* bk = (const float*)d_in[5];
    const float* Wv = (const float*)d_in[6];
    const float* bv = (const float*)d_in[7];
    const float* Wo = (const float*)d_in[8];
    const float* bo = (const float*)d_in[9];
    float* out = (float*)d_out;

    float *Op, *sx, *sa, *sw;
    int8_t *xq1, *xq0, *aq1, *aq0, *w1, *w0;
    cudaGetSymbolAddress((void**)&Op, g_O);
    cudaGetSymbolAddress((void**)&xq1, g_xq1);
    cudaGetSymbolAddress((void**)&xq0, g_xq0);
    cudaGetSymbolAddress((void**)&sx, g_sx);
    cudaGetSymbolAddress((void**)&aq1, g_aq1);
    cudaGetSymbolAddress((void**)&aq0, g_aq0);
    cudaGetSymbolAddress((void**)&sa, g_sa);
    cudaGetSymbolAddress((void**)&w1, g_w1);
    cudaGetSymbolAddress((void**)&w0, g_w0);
    cudaGetSymbolAddress((void**)&sw, g_sw);

    static int attr_set = 0;
    if (!attr_set) {
        cudaFuncSetAttribute(i8_gemm<true>,
                             cudaFuncAttributeMaxDynamicSharedMemorySize, GEMM_SMEM);
        cudaFuncSetAttribute(i8_gemm<false>,
                             cudaFuncAttributeMaxDynamicSharedMemorySize, GEMM_SMEM);
        cudaFuncSetAttribute(flash_mma,
                             cudaFuncAttributeMaxDynamicSharedMemorySize, FL_SMEM);
        attr_set = 1;
    }

    dim3 bW(32, 8);
    dim3 gWT(32, 32);

    // Quantize x (per-row) and weights (per-column, transposed) for fused QKV
    quant_rows<<<MM, 256>>>(x, xq1, xq0, sx);
    colmax_w<<<32, bW>>>(Wq, sw);
    colmax_w<<<32, bW>>>(Wk, sw + DD);
    colmax_w<<<32, bW>>>(Wv, sw + 2 * DD);
    quantw_t<<<gWT, bW>>>(Wq, sw, w1, w0);
    quantw_t<<<gWT, bW>>>(Wk, sw + DD, w1 + (size_t)DD * DD, w0 + (size_t)DD * DD);
    quantw_t<<<gWT, bW>>>(Wv, sw + 2 * DD, w1 + (size_t)2 * DD * DD, w0 + (size_t)2 * DD * DD);

    // Fused QKV projection (RoPE + layout in epilogue)
    dim3 gQKV(3 * DD / 128, MM / 128);  // (24, 32)
    i8_gemm<true><<<gQKV, 256, GEMM_SMEM>>>(xq1, xq0, sx, w1, w0, sw,
                                            bq, bk, bv, tp, nullptr);

    // Flash attention
    dim3 gFlash(SS / 64, HH, BB);
    flash_mma<<<gFlash, 128, FL_SMEM>>>();

    // O projection
    quant_rows<<<MM, 256>>>(Op, aq1, aq0, sa);
    colmax_w<<<32, bW>>>(Wo, sw);
    quantw_t<<<gWT, bW>>>(Wo, sw, w1, w0);
    dim3 gO(DD / 128, MM / 128);  // (8, 32)
    i8_gemm<false><<<gO, 256, GEMM_SMEM>>>(aq1, aq0, sa, w1, w0, sw,
                                           bo, bo, bo, tp, out);
}

// round 10
// speedup vs baseline: 1.9598x; 1.9598x over previous
#include <cuda_runtime.h>
#include <cuda_bf16.h>
#include <math.h>
#include <stdint.h>

// Problem constants
#define BB 2
#define SS 2048
#define DD 1024
#define HH 16
#define DKK 64
#define MM (BB * SS)          // 4096
#define SCALE 0.125f          // 1/sqrt(64)

// Scratch (allocation-free rule: __device__ globals)
__device__ float g_Q[BB * HH * SS * DKK];   // [B,H,S,DK] fp32 (pre-RoPE)
__device__ float g_K[BB * HH * SS * DKK];
__device__ __nv_bfloat16 g_Qhi[BB * HH * SS * DKK];  // post-RoPE hi/lo
__device__ __nv_bfloat16 g_Qlo[BB * HH * SS * DKK];
__device__ __nv_bfloat16 g_Khi[BB * HH * SS * DKK];
__device__ __nv_bfloat16 g_Klo[BB * HH * SS * DKK];
__device__ __nv_bfloat16 g_Vthi[BB * HH * DKK * SS]; // V transposed [b,h,dk,s]
__device__ __nv_bfloat16 g_Vtlo[BB * HH * DKK * SS];
__device__ __nv_bfloat16 g_xhi[MM * DD];
__device__ __nv_bfloat16 g_xlo[MM * DD];
__device__ __nv_bfloat16 g_ahi[MM * DD];    // attention output hi/lo (O-proj input)
__device__ __nv_bfloat16 g_alo[MM * DD];
__device__ __nv_bfloat16 g_whi[3 * DD * DD]; // W^T hi, 3 sections (QKV fused)
__device__ __nv_bfloat16 g_wlo[3 * DD * DD];

// ---------------------------------------------------------------------------
// Helpers
// ---------------------------------------------------------------------------
__device__ __forceinline__ uint32_t s2u(const void* p) {
    uint32_t a;
    asm("{ .reg .u64 t; cvta.to.shared.u64 t, %1; cvt.u32.u64 %0, t; }"
        : "=r"(a) : "l"(p));
    return a;
}
__device__ __forceinline__ void cp16(uint32_t dst, const void* src) {
    asm volatile("cp.async.cg.shared.global [%0], [%1], 16;" :: "r"(dst), "l"(src));
}
#define CP_COMMIT() asm volatile("cp.async.commit_group;" ::: "memory")
#define CP_WAIT1()  asm volatile("cp.async.wait_group 1;" ::: "memory")

__device__ __forceinline__ void mma16816(float* c, const uint32_t* a, const uint32_t* b)
{
    asm volatile(
        "mma.sync.aligned.m16n8k16.row.col.f32.bf16.bf16.f32 "
        "{%0,%1,%2,%3}, {%4,%5,%6,%7}, {%8,%9}, {%0,%1,%2,%3};"
        : "+f"(c[0]), "+f"(c[1]), "+f"(c[2]), "+f"(c[3])
        : "r"(a[0]), "r"(a[1]), "r"(a[2]), "r"(a[3]), "r"(b[0]), "r"(b[1]));
}
__device__ __forceinline__ uint32_t pack_bf2(float a, float b) {
    __nv_bfloat162 t = __floats2bfloat162_rn(a, b);
    return *(uint32_t*)&t;
}

// ---------------------------------------------------------------------------
// fp32 -> bf16 hi/lo split (elementwise)
// ---------------------------------------------------------------------------
__global__ __launch_bounds__(256) void convert_hl(
    const float* __restrict__ src, __nv_bfloat16* __restrict__ hi,
    __nv_bfloat16* __restrict__ lo, int n)
{
    int i = (blockIdx.x * blockDim.x + threadIdx.x) * 4;
    if (i >= n) return;
    float4 v = *(const float4*)(src + i);
    float f[4] = {v.x, v.y, v.z, v.w};
    __nv_bfloat16 h[4], l[4];
#pragma unroll
    for (int j = 0; j < 4; ++j) {
        h[j] = __float2bfloat16(f[j]);
        l[j] = __float2bfloat16(f[j] - __bfloat162float(h[j]));
    }
    *(uint2*)(hi + i) = *(uint2*)h;
    *(uint2*)(lo + i) = *(uint2*)l;
}

// ---------------------------------------------------------------------------
// W[k][n] -> Wt[n][k] bf16 hi/lo (tiled transpose). grid.z selects source /
// destination section for the fused QKV weight buffer.
// ---------------------------------------------------------------------------
__global__ __launch_bounds__(256) void convert_w3_t(
    const float* __restrict__ W0, const float* __restrict__ W1,
    const float* __restrict__ W2)
{
    __shared__ float t[32][33];
    const int sec = blockIdx.z;
    const float* W = (sec == 0) ? W0 : (sec == 1) ? W1 : W2;
    __nv_bfloat16* hi = g_whi + (size_t)sec * DD * DD;
    __nv_bfloat16* lo = g_wlo + (size_t)sec * DD * DD;
    int tx = threadIdx.x, ty = threadIdx.y;
    int kin = blockIdx.y * 32;
    int nin = blockIdx.x * 32;
#pragma unroll
    for (int j = 0; j < 4; ++j)
        t[ty + j * 8][tx] = W[(size_t)(kin + ty + j * 8) * DD + nin + tx];
    __syncthreads();
#pragma unroll
    for (int j = 0; j < 4; ++j) {
        float v = t[tx][ty + j * 8];
        __nv_bfloat16 h = __float2bfloat16(v);
        __nv_bfloat16 l = __float2bfloat16(v - __bfloat162float(h));
        size_t o = (size_t)(nin + ty + j * 8) * DD + kin + tx;
        hi[o] = h;
        lo[o] = l;
    }
}

// ---------------------------------------------------------------------------
// bf16x3 HMMA GEMM, CTA 128x128, 8 warps, BK=32, cp.async double buffer.
// QKV=true: fused N=3072 over g_whi/g_wlo; epilogue by section:
//   sec 0 -> fp32 g_Q [b,h,s,dk]; sec 1 -> fp32 g_K; sec 2 -> bf16 hi/lo V^T.
// QKV=false: fp32 out [m][n] + bias.
// ---------------------------------------------------------------------------
#define GEMM_SMEM 81920

template <bool QKV>
__global__ __launch_bounds__(256, 2) void mma_gemm(
    const __nv_bfloat16* __restrict__ Ahi, const __nv_bfloat16* __restrict__ Alo,
    const __nv_bfloat16* __restrict__ Bhi, const __nv_bfloat16* __restrict__ Blo,
    const float* __restrict__ b0p, const float* __restrict__ b1p,
    const float* __restrict__ b2p,
    float* __restrict__ outQ, float* __restrict__ outK)
{
    extern __shared__ char smem[];
    const uint32_t smem_u = s2u(smem);
    const int tid = threadIdx.x;
    const int lane = tid & 31;
    const int wid = tid >> 5;
    const int g = lane >> 2;
    const int tg = lane & 3;
    const int warp_m = wid & 1;
    const int warp_n = wid >> 1;
    const int n0 = blockIdx.x * 128;
    const int m0 = blockIdx.y * 128;

    float acc[4][4][4] = {};

    const int r_ = tid >> 2, c4 = tid & 3;

    auto load_stage = [&](int st, int kc) {
        const int k0 = kc * 32;
        const uint32_t sb = smem_u + st * 40960;
        {
            uint32_t d = sb + r_ * 80 + c4 * 16;
            size_t gsrc = (size_t)(m0 + r_) * DD + k0 + c4 * 8;
            cp16(d, Ahi + gsrc);
            cp16(d + 10240, Alo + gsrc);
            d += 64 * 80;  gsrc += (size_t)64 * DD;
            cp16(d, Ahi + gsrc);
            cp16(d + 10240, Alo + gsrc);
        }
        {
            uint32_t d = sb + 20480 + r_ * 80 + c4 * 16;
            size_t gsrc = (size_t)(n0 + r_) * DD + k0 + c4 * 8;
            cp16(d, Bhi + gsrc);
            cp16(d + 10240, Blo + gsrc);
            d += 64 * 80;  gsrc += (size_t)64 * DD;
            cp16(d, Bhi + gsrc);
            cp16(d + 10240, Blo + gsrc);
        }
    };

    load_stage(0, 0); CP_COMMIT();
    load_stage(1, 1); CP_COMMIT();

    for (int kc = 0; kc < 32; ++kc) {
        const int st = kc & 1;
        CP_WAIT1();
        __syncthreads();

        const char* sA = smem + st * 40960 + (warp_m * 64) * 80;
        const char* sB = smem + st * 40960 + 20480 + (warp_n * 32) * 80;

#pragma unroll
        for (int ks = 0; ks < 2; ++ks) {
            const int kb = ks * 32 + tg * 4;

            uint32_t bh[4][2], ah[4][4];
#pragma unroll
            for (int nt = 0; nt < 4; ++nt) {
                const char* p = sB + (nt * 8 + g) * 80 + kb;
                bh[nt][0] = *(const uint32_t*)p;
                bh[nt][1] = *(const uint32_t*)(p + 16);
            }
#pragma unroll
            for (int mt = 0; mt < 4; ++mt) {
                const char* p = sA + (mt * 16 + g) * 80 + kb;
                ah[mt][0] = *(const uint32_t*)p;
                ah[mt][1] = *(const uint32_t*)(p + 640);
                ah[mt][2] = *(const uint32_t*)(p + 16);
                ah[mt][3] = *(const uint32_t*)(p + 656);
            }
#pragma unroll
            for (int mt = 0; mt < 4; ++mt)
#pragma unroll
                for (int nt = 0; nt < 4; ++nt)
                    mma16816(acc[mt][nt], ah[mt], bh[nt]);

            uint32_t bl[4][2];
#pragma unroll
            for (int nt = 0; nt < 4; ++nt) {
                const char* p = sB + 10240 + (nt * 8 + g) * 80 + kb;
                bl[nt][0] = *(const uint32_t*)p;
                bl[nt][1] = *(const uint32_t*)(p + 16);
            }
#pragma unroll
            for (int mt = 0; mt < 4; ++mt)
#pragma unroll
                for (int nt = 0; nt < 4; ++nt)
                    mma16816(acc[mt][nt], ah[mt], bl[nt]);

            uint32_t al[4][4];
#pragma unroll
            for (int mt = 0; mt < 4; ++mt) {
                const char* p = sA + 10240 + (mt * 16 + g) * 80 + kb;
                al[mt][0] = *(const uint32_t*)p;
                al[mt][1] = *(const uint32_t*)(p + 640);
                al[mt][2] = *(const uint32_t*)(p + 16);
                al[mt][3] = *(const uint32_t*)(p + 656);
            }
#pragma unroll
            for (int mt = 0; mt < 4; ++mt)
#pragma unroll
                for (int nt = 0; nt < 4; ++nt)
                    mma16816(acc[mt][nt], al[mt], bh[nt]);
        }

        __syncthreads();
        if (kc + 2 < 32) load_stage(st, kc + 2);
        CP_COMMIT();
    }

    // ---- epilogue ----
    const int sec = QKV ? (n0 >> 10) : 0;   // uniform per CTA
    const float* bias = QKV ? ((sec == 0) ? b0p : (sec == 1) ? b1p : b2p) : b0p;

#pragma unroll
    for (int mt = 0; mt < 4; ++mt) {
        const int m = m0 + warp_m * 64 + mt * 16 + g;
#pragma unroll
        for (int nt = 0; nt < 4; ++nt) {
            const int nc = n0 + warp_n * 32 + nt * 8 + tg * 2;
            const int nl = QKV ? (nc & 1023) : nc;
            const float bv0 = __ldg(bias + nl), bv1 = __ldg(bias + nl + 1);
            float v00 = acc[mt][nt][0] + bv0, v01 = acc[mt][nt][1] + bv1;
            float v10 = acc[mt][nt][2] + bv0, v11 = acc[mt][nt][3] + bv1;
            if (QKV) {
                const int h = nl >> 6, dk = nl & 63;
                const int b_ = m >> 11, s = m & 2047;
                if (sec < 2) {
                    float* dst = (sec == 0) ? outQ : outK;
                    size_t base = (((size_t)(b_ * HH + h) * SS) + s) * DKK + dk;
                    *(float2*)(dst + base) = make_float2(v00, v01);
                    *(float2*)(dst + base + 8 * DKK) = make_float2(v10, v11);
                } else {
                    size_t base = (((size_t)(b_ * HH + h) * DKK) + dk) * SS + s;
                    float vv[4] = {v00, v01, v10, v11};
                    size_t off[4] = {base, base + SS, base + 8, base + SS + 8};
#pragma unroll
                    for (int e = 0; e < 4; ++e) {
                        __nv_bfloat16 hh = __float2bfloat16(vv[e]);
                        g_Vthi[off[e]] = hh;
                        g_Vtlo[off[e]] = __float2bfloat16(vv[e] - __bfloat162float(hh));
                    }
                }
            } else {
                *(float2*)(outQ + (size_t)m * DD + nc) = make_float2(v00, v01);
                *(float2*)(outQ + (size_t)(m + 8) * DD + nc) = make_float2(v10, v11);
            }
        }
    }
}

// ---------------------------------------------------------------------------
// RoPE: read fp32 g_Q/g_K, rotate, write bf16 hi/lo Q/K.
// ---------------------------------------------------------------------------
__global__ __launch_bounds__(256) void rope_kernel(const int* __restrict__ pos)
{
    __shared__ float invs[32];
    if (threadIdx.x < 32)
        invs[threadIdx.x] = (float)exp(-(double)threadIdx.x * 0.28782313662425575);
    __syncthreads();

    int idx = blockIdx.x * blockDim.x + threadIdx.x;
    if (idx >= BB * HH * SS * (DKK / 2)) return;
    int i = idx & 31;
    int s = (idx >> 5) & 2047;
    int h = (idx >> 16) & 15;
    int b = idx >> 20;

    int p = pos[b * SS + s];
    float ang = (float)p * invs[i];
    float c, sn;
    sincosf(ang, &sn, &c);

    size_t base = (((size_t)(b * HH + h) * SS) + s) * DKK + 2 * i;
    float q0 = g_Q[base], q1 = g_Q[base + 1];
    float qr0 = q0 * c - q1 * sn;
    float qr1 = q0 * sn + q1 * c;
    float k0 = g_K[base], k1 = g_K[base + 1];
    float kr0 = k0 * c - k1 * sn;
    float kr1 = k0 * sn + k1 * c;

    __nv_bfloat162 qh = __floats2bfloat162_rn(qr0, qr1);
    *(uint32_t*)(g_Qhi + base) = *(uint32_t*)&qh;
    __nv_bfloat162 ql = __floats2bfloat162_rn(qr0 - __bfloat162float(qh.x),
                                              qr1 - __bfloat162float(qh.y));
    *(uint32_t*)(g_Qlo + base) = *(uint32_t*)&ql;
    __nv_bfloat162 kh = __floats2bfloat162_rn(kr0, kr1);
    *(uint32_t*)(g_Khi + base) = *(uint32_t*)&kh;
    __nv_bfloat162 kl = __floats2bfloat162_rn(kr0 - __bfloat162float(kh.x),
                                              kr1 - __bfloat162float(kh.y));
    *(uint32_t*)(g_Klo + base) = *(uint32_t*)&kl;
}

// ---------------------------------------------------------------------------
// Flash attention with HMMA (bf16x3 split for QK and PV).
// CTA = 64 query rows of one (b,h); 128 threads, 4 warps.
// Output written as bf16 hi/lo directly into g_ahi/g_alo.
// ---------------------------------------------------------------------------
#define FL_PITCH 144
#define FL_TILE (64 * FL_PITCH)
#define FL_STAGE (4 * FL_TILE)
#define FL_SMEM (2 * FL_STAGE)

__global__ __launch_bounds__(128) void flash_mma()
{
    extern __shared__ char smem[];
    const int qt = (int)gridDim.x - 1 - (int)blockIdx.x;
    const int h = blockIdx.y;
    const int b = blockIdx.z;
    const int q0 = qt * 64;
    const int tid = threadIdx.x;
    const int lane = tid & 31;
    const int w = tid >> 5;
    const int g = lane >> 2;
    const int tg = lane & 3;

    const size_t bh = (size_t)(b * HH + h);
    const __nv_bfloat16* Qhi = g_Qhi + bh * SS * DKK;
    const __nv_bfloat16* Qlo = g_Qlo + bh * SS * DKK;
    const __nv_bfloat16* Khi = g_Khi + bh * SS * DKK;
    const __nv_bfloat16* Klo = g_Klo + bh * SS * DKK;
    const __nv_bfloat16* Vthi = g_Vthi + bh * DKK * SS;
    const __nv_bfloat16* Vtlo = g_Vtlo + bh * DKK * SS;

    const int qrow = q0 + w * 16 + g;
    uint32_t qh[4][4], ql[4][4];
#pragma unroll
    for (int kc = 0; kc < 4; ++kc) {
        size_t p0 = (size_t)qrow * DKK + kc * 16 + tg * 2;
        qh[kc][0] = *(const uint32_t*)(Qhi + p0);
        qh[kc][1] = *(const uint32_t*)(Qhi + p0 + 8 * DKK);
        qh[kc][2] = *(const uint32_t*)(Qhi + p0 + 8);
        qh[kc][3] = *(const uint32_t*)(Qhi + p0 + 8 * DKK + 8);
        ql[kc][0] = *(const uint32_t*)(Qlo + p0);
        ql[kc][1] = *(const uint32_t*)(Qlo + p0 + 8 * DKK);
        ql[kc][2] = *(const uint32_t*)(Qlo + p0 + 8);
        ql[kc][3] = *(const uint32_t*)(Qlo + p0 + 8 * DKK + 8);
    }

    auto load_stage = [&](int st, int t) {
        const int j0 = t * 64;
        char* sb = smem + st * FL_STAGE;
#pragma unroll
        for (int i = 0; i < 4; ++i) {
            int v = i * 128 + tid;
            int r = v >> 3, c = v & 7;
            uint32_t d = s2u(sb + r * FL_PITCH + c * 16);
            size_t ksrc = (size_t)(j0 + r) * DKK + c * 8;
            cp16(d, Khi + ksrc);
            cp16(d + FL_TILE, Klo + ksrc);
            size_t vsrc = (size_t)r * SS + j0 + c * 8;
            cp16(d + 2 * FL_TILE, Vthi + vsrc);
            cp16(d + 3 * FL_TILE, Vtlo + vsrc);
        }
    };

    float o[8][4] = {};
    float m_g = -1e30f, m_g8 = -1e30f;
    float l_g = 0.f, l_g8 = 0.f;

    const int nT = qt + 1;
    load_stage(0, 0); CP_COMMIT();
    if (nT > 1) load_stage(1, 1);
    CP_COMMIT();

    for (int t = 0; t < nT; ++t) {
        const int st = t & 1;
        CP_WAIT1();
        __syncthreads();

        const char* sK  = smem + st * FL_STAGE;
        const char* sKl = sK + FL_TILE;
        const char* sV  = sK + 2 * FL_TILE;
        const char* sVl = sK + 3 * FL_TILE;
        const int j0 = t * 64;

        float s[8][4] = {};
#pragma unroll
        for (int kc = 0; kc < 4; ++kc) {
            const int kb = kc * 32 + tg * 4;
            uint32_t kh[8][2], kl[8][2];
#pragma unroll
            for (int nf = 0; nf < 8; ++nf) {
                const char* p = sK + (nf * 8 + g) * FL_PITCH + kb;
                kh[nf][0] = *(const uint32_t*)p;
                kh[nf][1] = *(const uint32_t*)(p + 16);
                const char* p2 = sKl + (nf * 8 + g) * FL_PITCH + kb;
                kl[nf][0] = *(const uint32_t*)p2;
                kl[nf][1] = *(const uint32_t*)(p2 + 16);
            }
#pragma unroll
            for (int nf = 0; nf < 8; ++nf) {
                mma16816(s[nf], qh[kc], kh[nf]);
                mma16816(s[nf], qh[kc], kl[nf]);
                mma16816(s[nf], ql[kc], kh[nf]);
            }
        }

        const bool diag = (t == qt);
#pragma unroll
        for (int nf = 0; nf < 8; ++nf) {
#pragma unroll
            for (int e = 0; e < 4; ++e) {
                float v = s[nf][e] * SCALE;
                if (diag) {
                    int col = j0 + nf * 8 + tg * 2 + (e & 1);
                    int row = qrow + ((e >> 1) << 3);
                    if (col > row) v = -1e30f;
                }
                s[nf][e] = v;
            }
        }

        float tm_g = -1e30f, tm_g8 = -1e30f;
#pragma unroll
        for (int nf = 0; nf < 8; ++nf) {
            tm_g  = fmaxf(tm_g,  fmaxf(s[nf][0], s[nf][1]));
            tm_g8 = fmaxf(tm_g8, fmaxf(s[nf][2], s[nf][3]));
        }
        tm_g  = fmaxf(tm_g,  __shfl_xor_sync(0xffffffffu, tm_g, 1));
        tm_g  = fmaxf(tm_g,  __shfl_xor_sync(0xffffffffu, tm_g, 2));
        tm_g8 = fmaxf(tm_g8, __shfl_xor_sync(0xffffffffu, tm_g8, 1));
        tm_g8 = fmaxf(tm_g8, __shfl_xor_sync(0xffffffffu, tm_g8, 2));

        float mn_g = fmaxf(m_g, tm_g);
        float mn_g8 = fmaxf(m_g8, tm_g8);
        float alpha_g = expf(m_g - mn_g);
        float alpha_g8 = expf(m_g8 - mn_g8);
        m_g = mn_g; m_g8 = mn_g8;

        float sum_g = 0.f, sum_g8 = 0.f;
#pragma unroll
        for (int nf = 0; nf < 8; ++nf) {
            s[nf][0] = expf(s[nf][0] - mn_g);
            s[nf][1] = expf(s[nf][1] - mn_g);
            s[nf][2] = expf(s[nf][2] - mn_g8);
            s[nf][3] = expf(s[nf][3] - mn_g8);
            sum_g += s[nf][0] + s[nf][1];
            sum_g8 += s[nf][2] + s[nf][3];
        }
        sum_g  += __shfl_xor_sync(0xffffffffu, sum_g, 1);
        sum_g  += __shfl_xor_sync(0xffffffffu, sum_g, 2);
        sum_g8 += __shfl_xor_sync(0xffffffffu, sum_g8, 1);
        sum_g8 += __shfl_xor_sync(0xffffffffu, sum_g8, 2);
        l_g = l_g * alpha_g + sum_g;
        l_g8 = l_g8 * alpha_g8 + sum_g8;

#pragma unroll
        for (int nf = 0; nf < 8; ++nf) {
            o[nf][0] *= alpha_g;
            o[nf][1] *= alpha_g;
            o[nf][2] *= alpha_g8;
            o[nf][3] *= alpha_g8;
        }

#pragma unroll
        for (int kc = 0; kc < 4; ++kc) {
            uint32_t ph[4], pl[4];
            {
                const float* s0 = s[2 * kc];
                const float* s1 = s[2 * kc + 1];
                float h0 = __bfloat162float(__float2bfloat16(s0[0]));
                float h1 = __bfloat162float(__float2bfloat16(s0[1]));
                float h2 = __bfloat162float(__float2bfloat16(s0[2]));
                float h3 = __bfloat162float(__float2bfloat16(s0[3]));
                float h4 = __bfloat162float(__float2bfloat16(s1[0]));
                float h5 = __bfloat162float(__float2bfloat16(s1[1]));
                float h6 = __bfloat162float(__float2bfloat16(s1[2]));
                float h7 = __bfloat162float(__float2bfloat16(s1[3]));
                ph[0] = pack_bf2(h0, h1);
                ph[1] = pack_bf2(h2, h3);
                ph[2] = pack_bf2(h4, h5);
                ph[3] = pack_bf2(h6, h7);
                pl[0] = pack_bf2(s0[0] - h0, s0[1] - h1);
                pl[1] = pack_bf2(s0[2] - h2, s0[3] - h3);
                pl[2] = pack_bf2(s1[0] - h4, s1[1] - h5);
                pl[3] = pack_bf2(s1[2] - h6, s1[3] - h7);
            }
            const int kb = kc * 32 + tg * 4;
            uint32_t vh[8][2], vl[8][2];
#pragma unroll
            for (int nf = 0; nf < 8; ++nf) {
                const char* p = sV + (nf * 8 + g) * FL_PITCH + kb;
                vh[nf][0] = *(const uint32_t*)p;
                vh[nf][1] = *(const uint32_t*)(p + 16);
                const char* p2 = sVl + (nf * 8 + g) * FL_PITCH + kb;
                vl[nf][0] = *(const uint32_t*)p2;
                vl[nf][1] = *(const uint32_t*)(p2 + 16);
            }
#pragma unroll
            for (int nf = 0; nf < 8; ++nf) {
                mma16816(o[nf], ph, vh[nf]);
                mma16816(o[nf], ph, vl[nf]);
                mma16816(o[nf], pl, vh[nf]);
            }
        }

        __syncthreads();
        if (t + 2 < nT) load_stage(st, t + 2);
        CP_COMMIT();
    }

    const float inv_g = 1.0f / l_g;
    const float inv_g8 = 1.0f / l_g8;
#pragma unroll
    for (int nf = 0; nf < 8; ++nf) {
        const int col = h * DKK + nf * 8 + tg * 2;
        {
            float v0 = o[nf][0] * inv_g, v1 = o[nf][1] * inv_g;
            size_t addr = ((size_t)b * SS + qrow) * DD + col;
            __nv_bfloat162 hh = __floats2bfloat162_rn(v0, v1);
            *(uint32_t*)(g_ahi + addr) = *(uint32_t*)&hh;
            __nv_bfloat162 ll = __floats2bfloat162_rn(v0 - __bfloat162float(hh.x),
                                                      v1 - __bfloat162float(hh.y));
            *(uint32_t*)(g_alo + addr) = *(uint32_t*)&ll;
        }
        {
            float v0 = o[nf][2] * inv_g8, v1 = o[nf][3] * inv_g8;
            size_t addr = ((size_t)b * SS + qrow + 8) * DD + col;
            __nv_bfloat162 hh = __floats2bfloat162_rn(v0, v1);
            *(uint32_t*)(g_ahi + addr) = *(uint32_t*)&hh;
            __nv_bfloat162 ll = __floats2bfloat162_rn(v0 - __bfloat162float(hh.x),
                                                      v1 - __bfloat162float(hh.y));
            *(uint32_t*)(g_alo + addr) = *(uint32_t*)&ll;
        }
    }
}

// ---------------------------------------------------------------------------
extern "C" void kernel_launch(void* const* d_in, const int* in_sizes, int n_in,
                              void* d_out, int out_size)
{
    const float* x  = (const float*)d_in[0];
    const int*   tp = (const int*)d_in[1];
    const float* Wq = (const float*)d_in[2];
    const float* bq = (const float*)d_in[3];
    const float* Wk = (const float*)d_in[4];
    const float* bk = (const float*)d_in[5];
    const float* Wv = (const float*)d_in[6];
    const float* bv = (const float*)d_in[7];
    const float* Wo = (const float*)d_in[8];
    const float* bo = (const float*)d_in[9];
    float* out = (float*)d_out;

    float *Qp, *Kp;
    __nv_bfloat16 *xhi, *xlo, *ahi, *alo, *whi, *wlo;
    cudaGetSymbolAddress((void**)&Qp, g_Q);
    cudaGetSymbolAddress((void**)&Kp, g_K);
    cudaGetSymbolAddress((void**)&xhi, g_xhi);
    cudaGetSymbolAddress((void**)&xlo, g_xlo);
    cudaGetSymbolAddress((void**)&ahi, g_ahi);
    cudaGetSymbolAddress((void**)&alo, g_alo);
    cudaGetSymbolAddress((void**)&whi, g_whi);
    cudaGetSymbolAddress((void**)&wlo, g_wlo);

    static int attr_set = 0;
    if (!attr_set) {
        cudaFuncSetAttribute(mma_gemm<true>,
                             cudaFuncAttributeMaxDynamicSharedMemorySize, GEMM_SMEM);
        cudaFuncSetAttribute(mma_gemm<false>,
                             cudaFuncAttributeMaxDynamicSharedMemorySize, GEMM_SMEM);
        cudaFuncSetAttribute(flash_mma,
                             cudaFuncAttributeMaxDynamicSharedMemorySize, FL_SMEM);
        attr_set = 1;
    }

    const int nX = MM * DD;
    dim3 bW(32, 8);

    convert_hl<<<nX / 4 / 256, 256>>>(x, xhi, xlo, nX);
    convert_w3_t<<<dim3(32, 32, 3), bW>>>(Wq, Wk, Wv);

    // Fused QKV projection: one launch, N=3072 (768 CTAs -> ~2.6 waves)
    dim3 gQKV(3 * DD / 128, MM / 128);  // (24, 32)
    mma_gemm<true><<<gQKV, 256, GEMM_SMEM>>>(xhi, xlo, whi, wlo,
                                             bq, bk, bv, Qp, Kp);

    int ropeThreads = BB * HH * SS * (DKK / 2);
    rope_kernel<<<(ropeThreads + 255) / 256, 256>>>(tp);

    dim3 gFlash(SS / 64, HH, BB);
    flash_mma<<<gFlash, 128, FL_SMEM>>>();

    // O projection (reuse weight buffer section 0)
    convert_w3_t<<<dim3(32, 32, 1), bW>>>(Wo, Wo, Wo);
    dim3 gO(DD / 128, MM / 128);  // (8, 32)
    mma_gemm<false><<<gO, 256, GEMM_SMEM>>>(ahi, alo, whi, wlo,
                                            bo, bo, bo, out, nullptr);
}